// round 16
// baseline (speedup 1.0000x reference)
#include <cuda_runtime.h>
#include <cuda_fp16.h>
#include <math.h>

#define NB 2
#define NS 2048
#define ND 768
#define NH 12
#define NDK 64
#define NM (NB * NS)
#define XN (NM * ND)
#define WN (ND * ND)
#define NQT (NS / 128)   // 16 query tiles per (b,h)

// Half-precision copies of inputs (one-time conversion pass).
__device__ __half g_xh[3][XN];     // Q, K, V inputs
__device__ __half g_wh[4][WN];     // Wq, Wk, Wv, Wo
// Internal tensors (fp16, fp32 accumulate everywhere).
// g_q pre-scaled by 1/8. g_vt is V TRANSPOSED: [b][h][d][s].
__device__ __half g_q[(size_t)NB * NH * NS * NDK];
__device__ __half g_k[(size_t)NB * NH * NS * NDK];
__device__ __half g_vt[(size_t)NB * NH * NDK * NS];
__device__ __half g_ctx[(size_t)NB * NS * ND];

// ---------------------------------------------------------------------------
__device__ __forceinline__ unsigned packh2(float lo, float hi) {
    __half2 h = __floats2half2_rn(lo, hi);
    return *reinterpret_cast<unsigned*>(&h);
}

__device__ __forceinline__ void mma16(float d[4], const unsigned a[4], const unsigned b[2]) {
    asm volatile(
        "mma.sync.aligned.m16n8k16.row.col.f32.f16.f16.f32 "
        "{%0,%1,%2,%3}, {%4,%5,%6,%7}, {%8,%9}, {%0,%1,%2,%3};"
        : "+f"(d[0]), "+f"(d[1]), "+f"(d[2]), "+f"(d[3])
        : "r"(a[0]), "r"(a[1]), "r"(a[2]), "r"(a[3]), "r"(b[0]), "r"(b[1]));
}

__device__ __forceinline__ void ldm4(unsigned r[4], unsigned addr) {
    asm volatile("ldmatrix.sync.aligned.m8n8.x4.shared.b16 {%0,%1,%2,%3}, [%4];"
                 : "=r"(r[0]), "=r"(r[1]), "=r"(r[2]), "=r"(r[3]) : "r"(addr));
}

__device__ __forceinline__ unsigned smem_u32(const void* p) {
    return (unsigned)__cvta_generic_to_shared(p);
}
__device__ __forceinline__ void cp16(unsigned s, const void* g) {
    asm volatile("cp.async.cg.shared.global [%0], [%1], 16;" :: "r"(s), "l"(g));
}
__device__ __forceinline__ void cp_commit() {
    asm volatile("cp.async.commit_group;" ::: "memory");
}
template <int N>
__device__ __forceinline__ void cp_wait() {
    asm volatile("cp.async.wait_group %0;" :: "n"(N) : "memory");
}

// ---------------------------------------------------------------------------
// Conversion pass: fp32 inputs -> fp16 device globals (rn rounding).
// ---------------------------------------------------------------------------
__global__ __launch_bounds__(256) void convert_f2h(const float* __restrict__ X0,
                                                   const float* __restrict__ X1,
                                                   const float* __restrict__ X2,
                                                   const float* __restrict__ W0,
                                                   const float* __restrict__ W1,
                                                   const float* __restrict__ W2,
                                                   const float* __restrict__ W3) {
    const int seg = blockIdx.y;
    const float* src = (seg == 0) ? X0 : (seg == 1) ? X1 : (seg == 2) ? X2
                     : (seg == 3) ? W0 : (seg == 4) ? W1 : (seg == 5) ? W2 : W3;
    __half* dst = (seg < 3) ? g_xh[seg] : g_wh[seg - 3];
    const int n4 = ((seg < 3) ? XN : WN) / 4;
    for (int i = blockIdx.x * blockDim.x + threadIdx.x; i < n4;
         i += gridDim.x * blockDim.x) {
        float4 v = reinterpret_cast<const float4*>(src)[i];
        __half2 h0 = __floats2half2_rn(v.x, v.y);
        __half2 h1 = __floats2half2_rn(v.z, v.w);
        uint2 u;
        u.x = *reinterpret_cast<unsigned*>(&h0);
        u.y = *reinterpret_cast<unsigned*>(&h1);
        reinterpret_cast<uint2*>(dst)[i] = u;
    }
}

// ---------------------------------------------------------------------------
// QKV GEMM: g_{q,k,vt} = X @ W^T, fp16 smem + ldmatrix, fp32 accumulate.
// Block tile 128x128, 256 threads (8 warps, 2x4), warp tile 64x32, k-tile 64.
// grid.z selects Q/K/V; stores half head-split (Q *0.125, V transposed).
// ---------------------------------------------------------------------------
#define GSTR 72                 // smem row stride in halves
#define ATS (128 * GSTR)        // one 128-row stage, in halves
#define GEMM_SMEM (4 * ATS * 2) // 73728 bytes
#define NKT (ND / 64)           // 12 k-tiles

__global__ __launch_bounds__(256) void gemm_qkv() {
    extern __shared__ __half sm[];       // A stages @0, B stages @2*ATS

    const int z = blockIdx.z;
    const __half* X = g_xh[z];
    const __half* W = g_wh[z];

    const int tid = threadIdx.x;
    const int wid = tid >> 5, lane = tid & 31;
    const int wm = wid >> 2, wn = wid & 3;       // 2 x 4 warp grid
    const int gq = lane >> 2, gr = lane & 3;
    const int m0 = blockIdx.y * 128, n0 = blockIdx.x * 128;

    const int a_r = (lane & 7) + ((lane >> 3) & 1) * 8;
    const int a_c = (lane >> 4) * 8;
    const int b_r = (lane & 7) + ((lane >> 4) & 1) * 8;
    const int b_c = ((lane >> 3) & 1) * 8;

    float acc[4][4][4] = {};

    {
#pragma unroll
        for (int i = 0; i < 4; ++i) {
            const int slot = tid + i * 256;
            const int row = slot >> 3, c = (slot & 7) * 8;
            cp16(smem_u32(&sm[row * GSTR + c]), X + (size_t)(m0 + row) * ND + c);
            cp16(smem_u32(&sm[2 * ATS + row * GSTR + c]), W + (size_t)(n0 + row) * ND + c);
        }
        cp_commit();
    }

    for (int t = 0; t < NKT; ++t) {
        const int cur = t & 1;
        __syncthreads();
        if (t + 1 < NKT) {
            const int kn = (t + 1) * 64;
            const int nb = cur ^ 1;
#pragma unroll
            for (int i = 0; i < 4; ++i) {
                const int slot = tid + i * 256;
                const int row = slot >> 3, c = (slot & 7) * 8;
                cp16(smem_u32(&sm[nb * ATS + row * GSTR + c]),
                     X + (size_t)(m0 + row) * ND + kn + c);
                cp16(smem_u32(&sm[(2 + nb) * ATS + row * GSTR + c]),
                     W + (size_t)(n0 + row) * ND + kn + c);
            }
            cp_commit();
            cp_wait<1>();
        } else {
            cp_wait<0>();
        }
        __syncthreads();

        const __half* Ac = sm + cur * ATS;
        const __half* Bc = sm + (2 + cur) * ATS;
#pragma unroll
        for (int ks = 0; ks < 4; ++ks) {
            const int kb = ks * 16;
            unsigned af[4][4], bf[2][4];
#pragma unroll
            for (int mt = 0; mt < 4; ++mt) {
                const int rb = wm * 64 + mt * 16;
                ldm4(af[mt], smem_u32(Ac + (rb + a_r) * GSTR + kb + a_c));
            }
#pragma unroll
            for (int p = 0; p < 2; ++p) {
                const int nbr = wn * 32 + p * 16;
                ldm4(bf[p], smem_u32(Bc + (nbr + b_r) * GSTR + kb + b_c));
            }
#pragma unroll
            for (int mt = 0; mt < 4; ++mt) {
#pragma unroll
                for (int p = 0; p < 2; ++p) {
                    mma16(acc[mt][2 * p + 0], af[mt], &bf[p][0]);
                    mma16(acc[mt][2 * p + 1], af[mt], &bf[p][2]);
                }
            }
        }
    }

    const float escl = (z == 0) ? 0.125f : 1.0f;
#pragma unroll
    for (int mt = 0; mt < 4; ++mt) {
#pragma unroll
        for (int nt = 0; nt < 4; ++nt) {
#pragma unroll
            for (int half = 0; half < 2; ++half) {
                const int m = m0 + wm * 64 + mt * 16 + gq + half * 8;
                const int ncol = n0 + wn * 32 + nt * 8 + gr * 2;
                const float v0 = acc[mt][nt][half * 2 + 0];
                const float v1 = acc[mt][nt][half * 2 + 1];
                const int b = m >> 11, s = m & (NS - 1);
                const int h = ncol >> 6, dc = ncol & 63;
                if (z == 2) {
                    const size_t base = ((size_t)b * NH + h) * NDK;
                    g_vt[(base + dc) * NS + s] = __float2half_rn(v0);
                    g_vt[(base + dc + 1) * NS + s] = __float2half_rn(v1);
                } else {
                    __half* dst = (z == 0) ? g_q : g_k;
                    __half2* p = reinterpret_cast<__half2*>(
                        dst + (((size_t)b * NH + h) * NS + s) * NDK + dc);
                    *p = __floats2half2_rn(v0 * escl, v1 * escl);
                }
            }
        }
    }
}

// ---------------------------------------------------------------------------
// Output GEMM: out = ctx @ Wo^T, block tile 128x64, 128 threads (4 warps,
// 2m x 2n, warp tile 64x32 -- same inner shape as gemm_qkv), 4 blocks/SM.
// ---------------------------------------------------------------------------
#define BTS (64 * GSTR)
#define OGEMM_SMEM ((2 * ATS + 2 * BTS) * 2)   // 55296 bytes

__global__ __launch_bounds__(128, 4) void gemm_out(float* __restrict__ outp) {
    extern __shared__ __half sm[];       // A stages @0, B stages @2*ATS

    const __half* X = g_ctx;
    const __half* W = g_wh[3];

    const int tid = threadIdx.x;
    const int wid = tid >> 5, lane = tid & 31;
    const int wm = wid >> 1, wn = wid & 1;       // 2 x 2 warp grid
    const int gq = lane >> 2, gr = lane & 3;
    const int m0 = blockIdx.y * 128, n0 = blockIdx.x * 64;

    const int a_r = (lane & 7) + ((lane >> 3) & 1) * 8;
    const int a_c = (lane >> 4) * 8;
    const int b_r = (lane & 7) + ((lane >> 4) & 1) * 8;
    const int b_c = ((lane >> 3) & 1) * 8;

    float acc[4][4][4] = {};

    {
#pragma unroll
        for (int i = 0; i < 8; ++i) {
            const int slot = tid + i * 128;                 // 0..1023
            const int row = slot >> 3, c = (slot & 7) * 8;
            cp16(smem_u32(&sm[row * GSTR + c]), X + (size_t)(m0 + row) * ND + c);
        }
#pragma unroll
        for (int i = 0; i < 4; ++i) {
            const int slot = tid + i * 128;                 // 0..511
            const int row = slot >> 3, c = (slot & 7) * 8;
            cp16(smem_u32(&sm[2 * ATS + row * GSTR + c]), W + (size_t)(n0 + row) * ND + c);
        }
        cp_commit();
    }

    for (int t = 0; t < NKT; ++t) {
        const int cur = t & 1;
        __syncthreads();
        if (t + 1 < NKT) {
            const int kn = (t + 1) * 64;
            const int nb = cur ^ 1;
#pragma unroll
            for (int i = 0; i < 8; ++i) {
                const int slot = tid + i * 128;
                const int row = slot >> 3, c = (slot & 7) * 8;
                cp16(smem_u32(&sm[nb * ATS + row * GSTR + c]),
                     X + (size_t)(m0 + row) * ND + kn + c);
            }
#pragma unroll
            for (int i = 0; i < 4; ++i) {
                const int slot = tid + i * 128;
                const int row = slot >> 3, c = (slot & 7) * 8;
                cp16(smem_u32(&sm[2 * ATS + nb * BTS + row * GSTR + c]),
                     W + (size_t)(n0 + row) * ND + kn + c);
            }
            cp_commit();
            cp_wait<1>();
        } else {
            cp_wait<0>();
        }
        __syncthreads();

        const __half* Ac = sm + cur * ATS;
        const __half* Bc = sm + 2 * ATS + cur * BTS;
#pragma unroll
        for (int ks = 0; ks < 4; ++ks) {
            const int kb = ks * 16;
            unsigned af[4][4], bf[2][4];
#pragma unroll
            for (int mt = 0; mt < 4; ++mt) {
                const int rb = wm * 64 + mt * 16;
                ldm4(af[mt], smem_u32(Ac + (rb + a_r) * GSTR + kb + a_c));
            }
#pragma unroll
            for (int p = 0; p < 2; ++p) {
                const int nbr = wn * 32 + p * 16;
                ldm4(bf[p], smem_u32(Bc + (nbr + b_r) * GSTR + kb + b_c));
            }
#pragma unroll
            for (int mt = 0; mt < 4; ++mt) {
#pragma unroll
                for (int p = 0; p < 2; ++p) {
                    mma16(acc[mt][2 * p + 0], af[mt], &bf[p][0]);
                    mma16(acc[mt][2 * p + 1], af[mt], &bf[p][2]);
                }
            }
        }
    }

#pragma unroll
    for (int mt = 0; mt < 4; ++mt) {
#pragma unroll
        for (int nt = 0; nt < 4; ++nt) {
#pragma unroll
            for (int half = 0; half < 2; ++half) {
                const int m = m0 + wm * 64 + mt * 16 + gq + half * 8;
                const int ncol = n0 + wn * 32 + nt * 8 + gr * 2;
                outp[(size_t)m * ND + ncol] = acc[mt][nt][half * 2 + 0];
                outp[(size_t)m * ND + ncol + 1] = acc[mt][nt][half * 2 + 1];
            }
        }
    }
}

// ---------------------------------------------------------------------------
// Causal flash attention: fp16 MMA, fp32 softmax/accum.
// BM=128, BN=64, dk=64. 256 threads = 8 warps; warp owns 16 query rows.
// P in registers; K/V^T via ldmatrix; double-buffered cp.async.
// Longest-first block order; whole-warp skip of fully-masked key tiles.
// ---------------------------------------------------------------------------
#define FSTR 72
#define KVBUF_H (2 * 64 * FSTR)
#define FLASH_SMEM (2 * KVBUF_H * 2)     // 36864 bytes

__global__ __launch_bounds__(256, 2) void flash_mma() {
    extern __shared__ __half smh[];

    const int tid = threadIdx.x;
    const int wid = tid >> 5, lane = tid & 31;
    const int gq = lane >> 2, gr = lane & 3;
    const int qt = NQT - 1 - blockIdx.x;     // longest blocks first
    const int qb0 = qt * 128;
    const int bh = blockIdx.y;
    const int rb = wid * 16;

    const int b_r = (lane & 7) + ((lane >> 4) & 1) * 8;
    const int b_c = ((lane >> 3) & 1) * 8;

    const __half* qp = g_q + (size_t)bh * NS * NDK;
    const __half* kp = g_k + (size_t)bh * NS * NDK;
    const __half* vtp = g_vt + (size_t)bh * NDK * NS;

    // Q fragments from global (pre-rounded, pre-scaled).
    unsigned qf[4][4];
#pragma unroll
    for (int ks = 0; ks < 4; ++ks) {
        const int kb = ks * 16;
        qf[ks][0] = *reinterpret_cast<const unsigned*>(qp + (size_t)(qb0 + rb + gq) * NDK + kb + 2 * gr);
        qf[ks][1] = *reinterpret_cast<const unsigned*>(qp + (size_t)(qb0 + rb + 8 + gq) * NDK + kb + 2 * gr);
        qf[ks][2] = *reinterpret_cast<const unsigned*>(qp + (size_t)(qb0 + rb + gq) * NDK + kb + 2 * gr + 8);
        qf[ks][3] = *reinterpret_cast<const unsigned*>(qp + (size_t)(qb0 + rb + 8 + gq) * NDK + kb + 2 * gr + 8);
    }

    float o[8][4] = {};
    float mrow[2] = {-1e30f, -1e30f};
    float lrow[2] = {0.0f, 0.0f};

    const int njb = 2 * qt + 2;

    {
        __half* Kb = smh;
        __half* Vb = smh + 64 * FSTR;
#pragma unroll
        for (int i = 0; i < 2; ++i) {
            const int slot = tid + i * 256;
            const int r = slot >> 3, c8 = (slot & 7) * 8;
            cp16(smem_u32(Kb + r * FSTR + c8), kp + (size_t)r * NDK + c8);
            cp16(smem_u32(Vb + r * FSTR + c8), vtp + (size_t)r * NS + c8);
        }
        cp_commit();
    }

    for (int jb = 0; jb < njb; ++jb) {
        const int cur = jb & 1;
        __half* Ks = smh + cur * KVBUF_H;
        __half* Vs = Ks + 64 * FSTR;

        __syncthreads();
        if (jb + 1 < njb) {
            const int kn = (jb + 1) * 64;
            __half* Kb = smh + (cur ^ 1) * KVBUF_H;
            __half* Vb = Kb + 64 * FSTR;
#pragma unroll
            for (int i = 0; i < 2; ++i) {
                const int slot = tid + i * 256;
                const int r = slot >> 3, c8 = (slot & 7) * 8;
                cp16(smem_u32(Kb + r * FSTR + c8), kp + (size_t)(kn + r) * NDK + c8);
                cp16(smem_u32(Vb + r * FSTR + c8), vtp + (size_t)r * NS + kn + c8);
            }
            cp_commit();
            cp_wait<1>();
        } else {
            cp_wait<0>();
        }
        __syncthreads();

        const int k0 = jb * 64;
        // Whole-warp skip: tile fully above this warp's causal frontier.
        if (k0 > qb0 + rb + 15) continue;

        // S = Qtile @ K^T  (ldmatrix B-fragments, 16 keys per nt2)
        float s[8][4] = {};
#pragma unroll
        for (int ks = 0; ks < 4; ++ks) {
            const int kb = ks * 16;
#pragma unroll
            for (int nt2 = 0; nt2 < 4; ++nt2) {
                unsigned bf[4];
                ldm4(bf, smem_u32(Ks + (nt2 * 16 + b_r) * FSTR + kb + b_c));
                mma16(s[2 * nt2 + 0], qf[ks], &bf[0]);
                mma16(s[2 * nt2 + 1], qf[ks], &bf[2]);
            }
        }

        // Causal mask (only needed when the tile straddles the frontier)
        if (k0 + 63 > qb0 + rb) {
            const int qi0 = qb0 + rb + gq;
#pragma unroll
            for (int nt = 0; nt < 8; ++nt) {
                const int kj = k0 + nt * 8 + gr * 2;
                if (kj > qi0) s[nt][0] = -1e30f;
                if (kj + 1 > qi0) s[nt][1] = -1e30f;
                if (kj > qi0 + 8) s[nt][2] = -1e30f;
                if (kj + 1 > qi0 + 8) s[nt][3] = -1e30f;
            }
        }
        // Online softmax (fp32)
#pragma unroll
        for (int half = 0; half < 2; ++half) {
            float tmax = -1e30f;
#pragma unroll
            for (int nt = 0; nt < 8; ++nt)
                tmax = fmaxf(tmax, fmaxf(s[nt][half * 2], s[nt][half * 2 + 1]));
            tmax = fmaxf(tmax, __shfl_xor_sync(0xffffffffu, tmax, 1));
            tmax = fmaxf(tmax, __shfl_xor_sync(0xffffffffu, tmax, 2));
            const float mnew = fmaxf(mrow[half], tmax);
            const float scl = __expf(mrow[half] - mnew);
            float rsum = 0.0f;
#pragma unroll
            for (int nt = 0; nt < 8; ++nt) {
                const float p0 = __expf(s[nt][half * 2] - mnew);
                const float p1 = __expf(s[nt][half * 2 + 1] - mnew);
                s[nt][half * 2] = p0; s[nt][half * 2 + 1] = p1;
                rsum += p0 + p1;
            }
            rsum += __shfl_xor_sync(0xffffffffu, rsum, 1);
            rsum += __shfl_xor_sync(0xffffffffu, rsum, 2);
            lrow[half] = lrow[half] * scl + rsum;
            mrow[half] = mnew;
#pragma unroll
            for (int nt = 0; nt < 8; ++nt) {
                o[nt][half * 2] *= scl;
                o[nt][half * 2 + 1] *= scl;
            }
        }

        // O += P @ V : P stays in registers (QK D-frag == PV A-frag layout).
#pragma unroll
        for (int ks = 0; ks < 4; ++ks) {
            const int kb = ks * 16;
            unsigned af[4];
            af[0] = packh2(s[2 * ks][0], s[2 * ks][1]);
            af[1] = packh2(s[2 * ks][2], s[2 * ks][3]);
            af[2] = packh2(s[2 * ks + 1][0], s[2 * ks + 1][1]);
            af[3] = packh2(s[2 * ks + 1][2], s[2 * ks + 1][3]);
#pragma unroll
            for (int nt2 = 0; nt2 < 4; ++nt2) {
                unsigned bf[4];
                ldm4(bf, smem_u32(Vs + (nt2 * 16 + b_r) * FSTR + kb + b_c));
                mma16(o[2 * nt2 + 0], af, &bf[0]);
                mma16(o[2 * nt2 + 1], af, &bf[2]);
            }
        }
    }

    // Normalize (fp32), write ctx as half2
    const int b = bh / NH, h = bh % NH;
    const float inv0 = 1.0f / lrow[0], inv1 = 1.0f / lrow[1];
    const int s0 = qb0 + rb + gq;
#pragma unroll
    for (int nt = 0; nt < 8; ++nt) {
        const int dc = h * NDK + nt * 8 + 2 * gr;
        *reinterpret_cast<__half2*>(&g_ctx[((size_t)b * NS + s0) * ND + dc]) =
            __floats2half2_rn(o[nt][0] * inv0, o[nt][1] * inv0);
        *reinterpret_cast<__half2*>(&g_ctx[((size_t)b * NS + s0 + 8) * ND + dc]) =
            __floats2half2_rn(o[nt][2] * inv1, o[nt][3] * inv1);
    }
}

// ---------------------------------------------------------------------------
extern "C" void kernel_launch(void* const* d_in, const int* in_sizes, int n_in,
                              void* d_out, int out_size) {
    (void)in_sizes; (void)n_in; (void)out_size;
    const float* Q  = (const float*)d_in[0];
    const float* K  = (const float*)d_in[1];
    const float* V  = (const float*)d_in[2];
    const float* Wq = (const float*)d_in[4];
    const float* Wk = (const float*)d_in[5];
    const float* Wv = (const float*)d_in[6];
    const float* Wo = (const float*)d_in[7];
    float* out = (float*)d_out;

    cudaFuncSetAttribute(gemm_qkv, cudaFuncAttributeMaxDynamicSharedMemorySize, GEMM_SMEM);
    cudaFuncSetAttribute(gemm_out, cudaFuncAttributeMaxDynamicSharedMemorySize, OGEMM_SMEM);
    cudaFuncSetAttribute(flash_mma, cudaFuncAttributeMaxDynamicSharedMemorySize, FLASH_SMEM);

    // 1) fp32 -> fp16 conversion of X and W.
    convert_f2h<<<dim3(1024, 7), 256>>>(Q, K, V, Wq, Wk, Wv, Wo);

    // 2) Merged Q/K/V projection (576 blocks).
    gemm_qkv<<<dim3(ND / 128, NM / 128, 3), 256, GEMM_SMEM>>>();

    // 3) Flash attention (register-P, ldmatrix, longest-first).
    flash_mma<<<dim3(NQT, NB * NH), 256, FLASH_SMEM>>>();

    // 4) Output projection (384 blocks, 4 blocks/SM).
    gemm_out<<<dim3(ND / 64, NM / 128), 128, OGEMM_SMEM>>>(out);
}